// round 5
// baseline (speedup 1.0000x reference)
#include <cuda_runtime.h>
#include <cuda_bf16.h>
#include <cstdint>

#define BB 8
#define SS 2048
#define DD 512

// ---------------- device-global scratch (allocation-free) -------------------
__device__ __align__(16) __nv_bfloat16 g_xh[(size_t)BB * SS * DD];
__device__ __align__(16) __nv_bfloat16 g_xl[(size_t)BB * SS * DD];
__device__ __align__(16) __nv_bfloat16 g_wh[3 * DD * DD];
__device__ __align__(16) __nv_bfloat16 g_wl[3 * DD * DD];
__device__ __align__(16) __nv_bfloat16 g_qh[(size_t)BB * SS * DD];
__device__ __align__(16) __nv_bfloat16 g_ql[(size_t)BB * SS * DD];
__device__ __align__(16) __nv_bfloat16 g_kh[(size_t)BB * SS * DD];
__device__ __align__(16) __nv_bfloat16 g_kl[(size_t)BB * SS * DD];
__device__ __align__(16) __nv_bfloat16 g_vth[(size_t)BB * DD * SS];  // [b][d][s]
__device__ __align__(16) __nv_bfloat16 g_vtl[(size_t)BB * DD * SS];
__device__ __align__(16) float         g_sc [(size_t)BB * SS * SS];
__device__ __align__(16) __nv_bfloat16 g_ph[(size_t)BB * SS * SS];
__device__ __align__(16) __nv_bfloat16 g_pl[(size_t)BB * SS * SS];
__device__ int g_cnt[BB * 16];   // per (batch, 128-row band) completion counters

// ---------------- PTX helpers ----------------------------------------------
static __device__ __forceinline__ uint32_t su32(const void* p) {
    return (uint32_t)__cvta_generic_to_shared(p);
}
__device__ __forceinline__ void cp16(uint32_t dst, const void* src) {
    asm volatile("cp.async.cg.shared.global [%0], [%1], 16;" :: "r"(dst), "l"(src));
}
__device__ __forceinline__ void cp_commit() {
    asm volatile("cp.async.commit_group;" ::: "memory");
}
template <int N>
__device__ __forceinline__ void cp_wait() {
    asm volatile("cp.async.wait_group %0;" :: "n"(N) : "memory");
}
__device__ __forceinline__ void ldm_x4(uint32_t addr, uint32_t r[4]) {
    asm volatile("ldmatrix.sync.aligned.m8n8.x4.shared.b16 {%0,%1,%2,%3}, [%4];"
                 : "=r"(r[0]), "=r"(r[1]), "=r"(r[2]), "=r"(r[3]) : "r"(addr));
}
__device__ __forceinline__ void mma_bf16(float c[4], const uint32_t a[4], const uint32_t b[2]) {
    asm volatile(
        "mma.sync.aligned.m16n8k16.row.col.f32.bf16.bf16.f32 "
        "{%0,%1,%2,%3}, {%4,%5,%6,%7}, {%8,%9}, {%0,%1,%2,%3};"
        : "+f"(c[0]), "+f"(c[1]), "+f"(c[2]), "+f"(c[3])
        : "r"(a[0]), "r"(a[1]), "r"(a[2]), "r"(a[3]), "r"(b[0]), "r"(b[1]));
}
__device__ __forceinline__ uint32_t pack_split(float a, float b) {
    __nv_bfloat162 t(__float2bfloat16(a), __float2bfloat16(b));
    return *reinterpret_cast<uint32_t*>(&t);
}

// ---------------- pipelined block GEMM --------------------------------------
#define TPB 10240   // tile bytes (128 * 80)
#define STG 40960   // stage bytes

__device__ __forceinline__ void gemm_pipe(const __nv_bfloat16* __restrict__ Agh,
                                          const __nv_bfloat16* __restrict__ Agl,
                                          const __nv_bfloat16* __restrict__ Bgh,
                                          const __nv_bfloat16* __restrict__ Bgl,
                                          int K, int ldA, int ldB,
                                          char* smem, float acc[2][8][4]) {
    const int tid  = threadIdx.x;
    const int lane = tid & 31;
    const int w    = tid >> 5;
    const int wm   = w & 3;
    const int wn   = w >> 2;
    const int m0   = blockIdx.y * 128;
    const int n0   = blockIdx.x * 128;
    const uint32_t sbase = su32(smem);

#pragma unroll
    for (int mi = 0; mi < 2; mi++)
#pragma unroll
        for (int nj = 0; nj < 8; nj++)
#pragma unroll
            for (int e = 0; e < 4; e++) acc[mi][nj][e] = 0.0f;

    const int NK = K >> 5;
    const int r0 = tid >> 2, c0 = tid & 3;
    const int r1 = (tid + 256) >> 2, c1 = (tid + 256) & 3;

#define ISSUE(kidx, buf)                                                          \
    do {                                                                          \
        const int k0 = (kidx) << 5;                                               \
        uint32_t st = sbase + (buf) * STG;                                        \
        {                                                                         \
            size_t ga = (size_t)(m0 + r0) * ldA + k0 + c0 * 8;                    \
            size_t gb = (size_t)(n0 + r0) * ldB + k0 + c0 * 8;                    \
            uint32_t da = st + r0 * 80 + c0 * 16;                                 \
            cp16(da,            Agh + ga);                                        \
            cp16(da + TPB,      Agl + ga);                                        \
            cp16(da + 2 * TPB,  Bgh + gb);                                        \
            cp16(da + 3 * TPB,  Bgl + gb);                                        \
        }                                                                         \
        {                                                                         \
            size_t ga = (size_t)(m0 + r1) * ldA + k0 + c1 * 8;                    \
            size_t gb = (size_t)(n0 + r1) * ldB + k0 + c1 * 8;                    \
            uint32_t da = st + r1 * 80 + c1 * 16;                                 \
            cp16(da,            Agh + ga);                                        \
            cp16(da + TPB,      Agl + ga);                                        \
            cp16(da + 2 * TPB,  Bgh + gb);                                        \
            cp16(da + 3 * TPB,  Bgl + gb);                                        \
        }                                                                         \
        cp_commit();                                                              \
    } while (0)

    ISSUE(0, 0);

    for (int k = 0; k < NK; k++) {
        const int buf = k & 1;
        if (k + 1 < NK) { ISSUE(k + 1, buf ^ 1); cp_wait<1>(); }
        else            { cp_wait<0>(); }
        __syncthreads();

        const uint32_t sAh = sbase + buf * STG;
        const uint32_t sAl = sAh + TPB;
        const uint32_t sBh = sAh + 2 * TPB;
        const uint32_t sBl = sAh + 3 * TPB;

#pragma unroll
        for (int kk = 0; kk < 32; kk += 16) {
            uint32_t ah[2][4], al[2][4];
#pragma unroll
            for (int mi = 0; mi < 2; mi++) {
                uint32_t off = (uint32_t)(wm * 32 + mi * 16 + (lane & 15)) * 80
                             + (kk + (lane >> 4) * 8) * 2;
                ldm_x4(sAh + off, ah[mi]);
                ldm_x4(sAl + off, al[mi]);
            }
            uint32_t bh[8][2], bl[8][2];
#pragma unroll
            for (int nj4 = 0; nj4 < 4; nj4++) {
                uint32_t off = (uint32_t)(wn * 64 + nj4 * 16 + (lane & 7) + ((lane >> 4) << 3)) * 80
                             + (kk + (((lane >> 3) & 1) << 3)) * 2;
                uint32_t t[4];
                ldm_x4(sBh + off, t);
                bh[2 * nj4][0] = t[0]; bh[2 * nj4][1] = t[1];
                bh[2 * nj4 + 1][0] = t[2]; bh[2 * nj4 + 1][1] = t[3];
                ldm_x4(sBl + off, t);
                bl[2 * nj4][0] = t[0]; bl[2 * nj4][1] = t[1];
                bl[2 * nj4 + 1][0] = t[2]; bl[2 * nj4 + 1][1] = t[3];
            }
#pragma unroll
            for (int mi = 0; mi < 2; mi++)
#pragma unroll
                for (int nj = 0; nj < 8; nj++) {
                    mma_bf16(acc[mi][nj], ah[mi], bh[nj]);
                    mma_bf16(acc[mi][nj], ah[mi], bl[nj]);
                    mma_bf16(acc[mi][nj], al[mi], bh[nj]);
                }
        }
        __syncthreads();
    }
#undef ISSUE
}

// ---------------- epilogues --------------------------------------------------
__device__ __forceinline__ void store_acc_f32(float* __restrict__ C, int ldC,
                                              const float acc[2][8][4]) {
    const int lane = threadIdx.x & 31;
    const int w = threadIdx.x >> 5;
    const int wm = w & 3, wn = w >> 2;
    const int mb = blockIdx.y * 128 + wm * 32 + (lane >> 2);
    const int nb = blockIdx.x * 128 + wn * 64 + (lane & 3) * 2;
#pragma unroll
    for (int mi = 0; mi < 2; mi++) {
        int m = mb + mi * 16;
#pragma unroll
        for (int nj = 0; nj < 8; nj++) {
            int n = nb + nj * 8;
            *reinterpret_cast<float2*>(C + (size_t)m * ldC + n) =
                make_float2(acc[mi][nj][0], acc[mi][nj][1]);
            *reinterpret_cast<float2*>(C + (size_t)(m + 8) * ldC + n) =
                make_float2(acc[mi][nj][2], acc[mi][nj][3]);
        }
    }
}

__device__ __forceinline__ void store_acc_split(__nv_bfloat16* __restrict__ H,
                                                __nv_bfloat16* __restrict__ L,
                                                int ldC, const float acc[2][8][4]) {
    const int lane = threadIdx.x & 31;
    const int w = threadIdx.x >> 5;
    const int wm = w & 3, wn = w >> 2;
    const int mb = blockIdx.y * 128 + wm * 32 + (lane >> 2);
    const int nb = blockIdx.x * 128 + wn * 64 + (lane & 3) * 2;
#pragma unroll
    for (int mi = 0; mi < 2; mi++) {
        int m = mb + mi * 16;
#pragma unroll
        for (int nj = 0; nj < 8; nj++) {
            int n = nb + nj * 8;
#pragma unroll
            for (int half = 0; half < 2; half++) {
                float a = acc[mi][nj][half * 2], b = acc[mi][nj][half * 2 + 1];
                float ha = __bfloat162float(__float2bfloat16(a));
                float hb = __bfloat162float(__float2bfloat16(b));
                size_t idx = (size_t)(m + half * 8) * ldC + n;
                *reinterpret_cast<uint32_t*>(H + idx) = pack_split(a, b);
                *reinterpret_cast<uint32_t*>(L + idx) = pack_split(a - ha, b - hb);
            }
        }
    }
}

// ---------------- kernels ----------------------------------------------------
__global__ void __launch_bounds__(256)
split_kernel(const float* __restrict__ src, __nv_bfloat16* __restrict__ h,
             __nv_bfloat16* __restrict__ l, int n4) {
    int i = blockIdx.x * blockDim.x + threadIdx.x;
    if (i >= n4) return;
    float4 v = reinterpret_cast<const float4*>(src)[i];
    float hx = __bfloat162float(__float2bfloat16(v.x));
    float hy = __bfloat162float(__float2bfloat16(v.y));
    float hz = __bfloat162float(__float2bfloat16(v.z));
    float hw = __bfloat162float(__float2bfloat16(v.w));
    uint2 hv = make_uint2(pack_split(v.x, v.y), pack_split(v.z, v.w));
    uint2 lv = make_uint2(pack_split(v.x - hx, v.y - hy), pack_split(v.z - hz, v.w - hw));
    reinterpret_cast<uint2*>(h)[i] = hv;
    reinterpret_cast<uint2*>(l)[i] = lv;
}

__global__ void zero_cnt() {
    if (threadIdx.x < BB * 16) g_cnt[threadIdx.x] = 0;
}

// QKV: grid=(4, 128, 3). z: 0=Q, 1=K, 2=V(transposed split store)
__global__ void __launch_bounds__(256, 2)
qkv_mm(int dummy) {
    extern __shared__ char smem[];
    const int z = blockIdx.z;
    float acc[2][8][4];
    gemm_pipe(g_xh, g_xl, g_wh + z * DD * DD, g_wl + z * DD * DD,
              DD, DD, DD, smem, acc);

    if (z == 0)      store_acc_split(g_qh, g_ql, DD, acc);
    else if (z == 1) store_acc_split(g_kh, g_kl, DD, acc);
    else {
        const int lane = threadIdx.x & 31;
        const int w = threadIdx.x >> 5;
        const int wm = w & 3, wn = w >> 2;
        const int mb = blockIdx.y * 128 + wm * 32 + (lane >> 2);
        const int nb = blockIdx.x * 128 + wn * 64 + (lane & 3) * 2;
        const int b = mb >> 11;
        __nv_bfloat16* vh = g_vth + (size_t)b * DD * SS;
        __nv_bfloat16* vl = g_vtl + (size_t)b * DD * SS;
#pragma unroll
        for (int mi = 0; mi < 2; mi++) {
            int s = (mb & 2047) + mi * 16;
#pragma unroll
            for (int nj = 0; nj < 8; nj++) {
                int d = nb + nj * 8;
#pragma unroll
                for (int e = 0; e < 4; e++) {
                    float v = acc[mi][nj][e];
                    float hv = __bfloat162float(__float2bfloat16(v));
                    size_t idx = (size_t)(d + (e & 1)) * SS + s + (e >> 1) * 8;
                    vh[idx] = __float2bfloat16(v);
                    vl[idx] = __float2bfloat16(v - hv);
                }
            }
        }
    }
}

// scores + fused band softmax: grid=(16,16,8)
__global__ void __launch_bounds__(256, 2)
scores_mm(const int* __restrict__ mask) {
    extern __shared__ char smem[];
    const int b = blockIdx.z;
    float acc[2][8][4];
    gemm_pipe(g_qh + (size_t)b * SS * DD, g_ql + (size_t)b * SS * DD,
              g_kh + (size_t)b * SS * DD, g_kl + (size_t)b * SS * DD,
              DD, DD, DD, smem, acc);

    const int lane = threadIdx.x & 31;
    const int w = threadIdx.x >> 5;
    const int wm = w & 3, wn = w >> 2;
    const int mb = blockIdx.y * 128 + wm * 32 + (lane >> 2);
    const int nb = blockIdx.x * 128 + wn * 64 + (lane & 3) * 2;
    const float inv_scale = 0.0220970869120796101f;  // 1/sqrt(2048)
    float* Scb = g_sc + (size_t)b * SS * SS;
    const int* mrow = mask + b * SS;

#pragma unroll
    for (int nj = 0; nj < 8; nj++) {
        int n = nb + nj * 8;
        float f0 = mrow[n]     ? inv_scale : 0.0f;
        float g0 = mrow[n]     ? 0.0f      : -1e30f;
        float f1 = mrow[n + 1] ? inv_scale : 0.0f;
        float g1 = mrow[n + 1] ? 0.0f      : -1e30f;
#pragma unroll
        for (int mi = 0; mi < 2; mi++) {
            int m = mb + mi * 16;
            *reinterpret_cast<float2*>(Scb + (size_t)m * SS + n) =
                make_float2(acc[mi][nj][0] * f0 + g0, acc[mi][nj][1] * f1 + g1);
            *reinterpret_cast<float2*>(Scb + (size_t)(m + 8) * SS + n) =
                make_float2(acc[mi][nj][2] * f0 + g0, acc[mi][nj][3] * f1 + g1);
        }
    }

    // ---- band completion: last of the 16 x-CTAs runs softmax for this band ----
    __threadfence();
    __shared__ int s_old;
    if (threadIdx.x == 0)
        s_old = atomicAdd(&g_cnt[b * 16 + blockIdx.y], 1);
    __syncthreads();
    if (s_old != 15) return;
    __threadfence();

    const size_t boff = (size_t)b * SS * SS + (size_t)(blockIdx.y * 128) * SS;
    float* band = g_sc + boff;
    __nv_bfloat16* PH = g_ph + boff;
    __nv_bfloat16* PL = g_pl + boff;

    // 8 warps x 16 rows each; one warp owns a full 2048-wide row.
    for (int i = 0; i < 16; i++) {
        const int r = w * 16 + i;
        const float4* row4 = reinterpret_cast<const float4*>(band + (size_t)r * SS);
        float4 v[16];
        float mx = -1e38f;
#pragma unroll
        for (int j = 0; j < 16; j++) {
            v[j] = row4[lane + j * 32];
            mx = fmaxf(mx, fmaxf(fmaxf(v[j].x, v[j].y), fmaxf(v[j].z, v[j].w)));
        }
#pragma unroll
        for (int o = 16; o > 0; o >>= 1) mx = fmaxf(mx, __shfl_xor_sync(0xffffffffu, mx, o));

        float sum = 0.0f;
#pragma unroll
        for (int j = 0; j < 16; j++) {
            v[j].x = __expf(v[j].x - mx);
            v[j].y = __expf(v[j].y - mx);
            v[j].z = __expf(v[j].z - mx);
            v[j].w = __expf(v[j].w - mx);
            sum += (v[j].x + v[j].y) + (v[j].z + v[j].w);
        }
#pragma unroll
        for (int o = 16; o > 0; o >>= 1) sum += __shfl_xor_sync(0xffffffffu, sum, o);
        const float rinv = 1.0f / sum;

        uint2* ph2 = reinterpret_cast<uint2*>(PH + (size_t)r * SS);
        uint2* pl2 = reinterpret_cast<uint2*>(PL + (size_t)r * SS);
#pragma unroll
        for (int j = 0; j < 16; j++) {
            float px = v[j].x * rinv, py = v[j].y * rinv;
            float pz = v[j].z * rinv, pw = v[j].w * rinv;
            float hx = __bfloat162float(__float2bfloat16(px));
            float hy = __bfloat162float(__float2bfloat16(py));
            float hz = __bfloat162float(__float2bfloat16(pz));
            float hw = __bfloat162float(__float2bfloat16(pw));
            ph2[lane + j * 32] = make_uint2(pack_split(px, py), pack_split(pz, pw));
            pl2[lane + j * 32] = make_uint2(pack_split(px - hx, py - hy),
                                            pack_split(pz - hz, pw - hw));
        }
    }
}

// PV: grid=(4,16,8)
__global__ void __launch_bounds__(256, 2)
pv_mm(float* __restrict__ out) {
    extern __shared__ char smem[];
    const int b = blockIdx.z;
    float acc[2][8][4];
    gemm_pipe(g_ph + (size_t)b * SS * SS, g_pl + (size_t)b * SS * SS,
              g_vth + (size_t)b * DD * SS, g_vtl + (size_t)b * DD * SS,
              SS, SS, SS, smem, acc);
    store_acc_f32(out + (size_t)b * SS * DD, DD, acc);
}

// ---------------------------------------------------------------------------
extern "C" void kernel_launch(void* const* d_in, const int* in_sizes, int n_in,
                              void* d_out, int out_size) {
    const float* X    = (const float*)d_in[0];
    const int*   mask = (const int*)  d_in[1];
    const float* Wq   = (const float*)d_in[2];
    const float* Wk   = (const float*)d_in[3];
    const float* Wv   = (const float*)d_in[4];
    float* out = (float*)d_out;

    static bool attr_done = false;
    if (!attr_done) {
        cudaFuncSetAttribute(qkv_mm,    cudaFuncAttributeMaxDynamicSharedMemorySize, 2 * STG);
        cudaFuncSetAttribute(scores_mm, cudaFuncAttributeMaxDynamicSharedMemorySize, 2 * STG);
        cudaFuncSetAttribute(pv_mm,     cudaFuncAttributeMaxDynamicSharedMemorySize, 2 * STG);
        attr_done = true;
    }

    __nv_bfloat16 *xh, *xl, *wh, *wl;
    cudaGetSymbolAddress((void**)&xh, g_xh);
    cudaGetSymbolAddress((void**)&xl, g_xl);
    cudaGetSymbolAddress((void**)&wh, g_wh);
    cudaGetSymbolAddress((void**)&wl, g_wl);

    const int nX4 = (BB * SS * DD) / 4;
    const int nW4 = (DD * DD) / 4;
    split_kernel<<<(nX4 + 255) / 256, 256>>>(X, xh, xl, nX4);
    split_kernel<<<(nW4 + 255) / 256, 256>>>(Wq, wh,            wl,            nW4);
    split_kernel<<<(nW4 + 255) / 256, 256>>>(Wk, wh + DD * DD,  wl + DD * DD,  nW4);
    split_kernel<<<(nW4 + 255) / 256, 256>>>(Wv, wh + 2*DD*DD,  wl + 2*DD*DD,  nW4);
    zero_cnt<<<1, 128>>>();

    dim3 blk(256);
    qkv_mm<<<dim3(DD / 128, (BB * SS) / 128, 3), blk, 2 * STG>>>(0);
    scores_mm<<<dim3(SS / 128, SS / 128, BB), blk, 2 * STG>>>(mask);
    pv_mm<<<dim3(DD / 128, SS / 128, BB), blk, 2 * STG>>>(out);
}

// round 6
// speedup vs baseline: 1.4768x; 1.4768x over previous
#include <cuda_runtime.h>
#include <cuda_bf16.h>
#include <cstdint>

#define BB 8
#define SS 2048
#define DD 512

// ---------------- device-global scratch (allocation-free) -------------------
__device__ __align__(16) __nv_bfloat16 g_xh[(size_t)BB * SS * DD];
__device__ __align__(16) __nv_bfloat16 g_xl[(size_t)BB * SS * DD];
__device__ __align__(16) __nv_bfloat16 g_wh[3 * DD * DD];
__device__ __align__(16) __nv_bfloat16 g_wl[3 * DD * DD];
__device__ __align__(16) __nv_bfloat16 g_qh[(size_t)BB * SS * DD];
__device__ __align__(16) __nv_bfloat16 g_ql[(size_t)BB * SS * DD];
__device__ __align__(16) __nv_bfloat16 g_kh[(size_t)BB * SS * DD];   // compacted rows
__device__ __align__(16) __nv_bfloat16 g_kl[(size_t)BB * SS * DD];
__device__ __align__(16) __nv_bfloat16 g_vth[(size_t)BB * DD * SS];  // [b][d][slot]
__device__ __align__(16) __nv_bfloat16 g_vtl[(size_t)BB * DD * SS];
__device__ __align__(16) float         g_sc [(size_t)BB * SS * SS];
__device__ __align__(16) __nv_bfloat16 g_ph[(size_t)BB * SS * SS];
__device__ __align__(16) __nv_bfloat16 g_pl[(size_t)BB * SS * SS];
__device__ int g_slot[BB * SS];   // s -> compacted slot (-1 if masked)
__device__ int g_nvalid[BB];
__device__ int g_npad[BB];

// ---------------- PTX helpers ----------------------------------------------
static __device__ __forceinline__ uint32_t su32(const void* p) {
    return (uint32_t)__cvta_generic_to_shared(p);
}
__device__ __forceinline__ void cp16(uint32_t dst, const void* src) {
    asm volatile("cp.async.cg.shared.global [%0], [%1], 16;" :: "r"(dst), "l"(src));
}
__device__ __forceinline__ void cp_commit() {
    asm volatile("cp.async.commit_group;" ::: "memory");
}
template <int N>
__device__ __forceinline__ void cp_wait() {
    asm volatile("cp.async.wait_group %0;" :: "n"(N) : "memory");
}
__device__ __forceinline__ void ldm_x4(uint32_t addr, uint32_t r[4]) {
    asm volatile("ldmatrix.sync.aligned.m8n8.x4.shared.b16 {%0,%1,%2,%3}, [%4];"
                 : "=r"(r[0]), "=r"(r[1]), "=r"(r[2]), "=r"(r[3]) : "r"(addr));
}
__device__ __forceinline__ void mma_bf16(float c[4], const uint32_t a[4], const uint32_t b[2]) {
    asm volatile(
        "mma.sync.aligned.m16n8k16.row.col.f32.bf16.bf16.f32 "
        "{%0,%1,%2,%3}, {%4,%5,%6,%7}, {%8,%9}, {%0,%1,%2,%3};"
        : "+f"(c[0]), "+f"(c[1]), "+f"(c[2]), "+f"(c[3])
        : "r"(a[0]), "r"(a[1]), "r"(a[2]), "r"(a[3]), "r"(b[0]), "r"(b[1]));
}
__device__ __forceinline__ uint32_t pack_split(float a, float b) {
    __nv_bfloat162 t(__float2bfloat16(a), __float2bfloat16(b));
    return *reinterpret_cast<uint32_t*>(&t);
}
__device__ __forceinline__ float bfv(float a) {
    return __bfloat162float(__float2bfloat16(a));
}

// ---------------- pipelined block GEMM --------------------------------------
#define TPB 10240   // tile bytes (128 * 80)
#define STG 40960   // stage bytes

__device__ __forceinline__ void gemm_pipe(const __nv_bfloat16* __restrict__ Agh,
                                          const __nv_bfloat16* __restrict__ Agl,
                                          const __nv_bfloat16* __restrict__ Bgh,
                                          const __nv_bfloat16* __restrict__ Bgl,
                                          int K, int ldA, int ldB,
                                          char* smem, float acc[2][8][4]) {
    const int tid  = threadIdx.x;
    const int lane = tid & 31;
    const int w    = tid >> 5;
    const int wm   = w & 3;
    const int wn   = w >> 2;
    const int m0   = blockIdx.y * 128;
    const int n0   = blockIdx.x * 128;
    const uint32_t sbase = su32(smem);

#pragma unroll
    for (int mi = 0; mi < 2; mi++)
#pragma unroll
        for (int nj = 0; nj < 8; nj++)
#pragma unroll
            for (int e = 0; e < 4; e++) acc[mi][nj][e] = 0.0f;

    const int NK = K >> 5;
    const int r0 = tid >> 2, c0 = tid & 3;
    const int r1 = (tid + 256) >> 2, c1 = (tid + 256) & 3;

#define ISSUE(kidx, buf)                                                          \
    do {                                                                          \
        const int k0 = (kidx) << 5;                                               \
        uint32_t st = sbase + (buf) * STG;                                        \
        {                                                                         \
            size_t ga = (size_t)(m0 + r0) * ldA + k0 + c0 * 8;                    \
            size_t gb = (size_t)(n0 + r0) * ldB + k0 + c0 * 8;                    \
            uint32_t da = st + r0 * 80 + c0 * 16;                                 \
            cp16(da,            Agh + ga);                                        \
            cp16(da + TPB,      Agl + ga);                                        \
            cp16(da + 2 * TPB,  Bgh + gb);                                        \
            cp16(da + 3 * TPB,  Bgl + gb);                                        \
        }                                                                         \
        {                                                                         \
            size_t ga = (size_t)(m0 + r1) * ldA + k0 + c1 * 8;                    \
            size_t gb = (size_t)(n0 + r1) * ldB + k0 + c1 * 8;                    \
            uint32_t da = st + r1 * 80 + c1 * 16;                                 \
            cp16(da,            Agh + ga);                                        \
            cp16(da + TPB,      Agl + ga);                                        \
            cp16(da + 2 * TPB,  Bgh + gb);                                        \
            cp16(da + 3 * TPB,  Bgl + gb);                                        \
        }                                                                         \
        cp_commit();                                                              \
    } while (0)

    ISSUE(0, 0);

    for (int k = 0; k < NK; k++) {
        const int buf = k & 1;
        if (k + 1 < NK) { ISSUE(k + 1, buf ^ 1); cp_wait<1>(); }
        else            { cp_wait<0>(); }
        __syncthreads();

        const uint32_t sAh = sbase + buf * STG;
        const uint32_t sAl = sAh + TPB;
        const uint32_t sBh = sAh + 2 * TPB;
        const uint32_t sBl = sAh + 3 * TPB;

#pragma unroll
        for (int kk = 0; kk < 32; kk += 16) {
            uint32_t ah[2][4], al[2][4];
#pragma unroll
            for (int mi = 0; mi < 2; mi++) {
                uint32_t off = (uint32_t)(wm * 32 + mi * 16 + (lane & 15)) * 80
                             + (kk + (lane >> 4) * 8) * 2;
                ldm_x4(sAh + off, ah[mi]);
                ldm_x4(sAl + off, al[mi]);
            }
            uint32_t bh[8][2], bl[8][2];
#pragma unroll
            for (int nj4 = 0; nj4 < 4; nj4++) {
                uint32_t off = (uint32_t)(wn * 64 + nj4 * 16 + (lane & 7) + ((lane >> 4) << 3)) * 80
                             + (kk + (((lane >> 3) & 1) << 3)) * 2;
                uint32_t t[4];
                ldm_x4(sBh + off, t);
                bh[2 * nj4][0] = t[0]; bh[2 * nj4][1] = t[1];
                bh[2 * nj4 + 1][0] = t[2]; bh[2 * nj4 + 1][1] = t[3];
                ldm_x4(sBl + off, t);
                bl[2 * nj4][0] = t[0]; bl[2 * nj4][1] = t[1];
                bl[2 * nj4 + 1][0] = t[2]; bl[2 * nj4 + 1][1] = t[3];
            }
#pragma unroll
            for (int mi = 0; mi < 2; mi++)
#pragma unroll
                for (int nj = 0; nj < 8; nj++) {
                    mma_bf16(acc[mi][nj], ah[mi], bh[nj]);
                    mma_bf16(acc[mi][nj], ah[mi], bl[nj]);
                    mma_bf16(acc[mi][nj], al[mi], bh[nj]);
                }
        }
        __syncthreads();
    }
#undef ISSUE
}

// ---------------- epilogues --------------------------------------------------
__device__ __forceinline__ void store_acc_f32(float* __restrict__ C, int ldC,
                                              const float acc[2][8][4]) {
    const int lane = threadIdx.x & 31;
    const int w = threadIdx.x >> 5;
    const int wm = w & 3, wn = w >> 2;
    const int mb = blockIdx.y * 128 + wm * 32 + (lane >> 2);
    const int nb = blockIdx.x * 128 + wn * 64 + (lane & 3) * 2;
#pragma unroll
    for (int mi = 0; mi < 2; mi++) {
        int m = mb + mi * 16;
#pragma unroll
        for (int nj = 0; nj < 8; nj++) {
            int n = nb + nj * 8;
            *reinterpret_cast<float2*>(C + (size_t)m * ldC + n) =
                make_float2(acc[mi][nj][0], acc[mi][nj][1]);
            *reinterpret_cast<float2*>(C + (size_t)(m + 8) * ldC + n) =
                make_float2(acc[mi][nj][2], acc[mi][nj][3]);
        }
    }
}

__device__ __forceinline__ void store_acc_split(__nv_bfloat16* __restrict__ H,
                                                __nv_bfloat16* __restrict__ L,
                                                int ldC, const float acc[2][8][4]) {
    const int lane = threadIdx.x & 31;
    const int w = threadIdx.x >> 5;
    const int wm = w & 3, wn = w >> 2;
    const int mb = blockIdx.y * 128 + wm * 32 + (lane >> 2);
    const int nb = blockIdx.x * 128 + wn * 64 + (lane & 3) * 2;
#pragma unroll
    for (int mi = 0; mi < 2; mi++) {
        int m = mb + mi * 16;
#pragma unroll
        for (int nj = 0; nj < 8; nj++) {
            int n = nb + nj * 8;
#pragma unroll
            for (int half = 0; half < 2; half++) {
                float a = acc[mi][nj][half * 2], b = acc[mi][nj][half * 2 + 1];
                size_t idx = (size_t)(m + half * 8) * ldC + n;
                *reinterpret_cast<uint32_t*>(H + idx) = pack_split(a, b);
                *reinterpret_cast<uint32_t*>(L + idx) =
                    pack_split(a - bfv(a), b - bfv(b));
            }
        }
    }
}

// ---------------- kernels ----------------------------------------------------
__global__ void __launch_bounds__(256)
split_kernel(const float* __restrict__ src, __nv_bfloat16* __restrict__ h,
             __nv_bfloat16* __restrict__ l, int n4) {
    int i = blockIdx.x * blockDim.x + threadIdx.x;
    if (i >= n4) return;
    float4 v = reinterpret_cast<const float4*>(src)[i];
    reinterpret_cast<uint2*>(h)[i] = make_uint2(pack_split(v.x, v.y), pack_split(v.z, v.w));
    reinterpret_cast<uint2*>(l)[i] = make_uint2(pack_split(v.x - bfv(v.x), v.y - bfv(v.y)),
                                                pack_split(v.z - bfv(v.z), v.w - bfv(v.w)));
}

// per-batch compaction index (1 block per batch, 256 threads x 8 elems)
__global__ void __launch_bounds__(256)
build_index(const int* __restrict__ mask) {
    const int b = blockIdx.x;
    const int t = threadIdx.x;
    const int* m = mask + b * SS;
    const int base = t * 8;
    int loc[8], cnt = 0;
#pragma unroll
    for (int i = 0; i < 8; i++) { loc[i] = (m[base + i] != 0); cnt += loc[i]; }
    const int lane = t & 31, w = t >> 5;
    int v = cnt;
#pragma unroll
    for (int o = 1; o < 32; o <<= 1) {
        int u = __shfl_up_sync(0xffffffffu, v, o);
        if (lane >= o) v += u;
    }
    __shared__ int ws[8];
    if (lane == 31) ws[w] = v;
    __syncthreads();
    int wo = 0;
#pragma unroll
    for (int i = 0; i < 8; i++) if (i < w) wo += ws[i];
    int excl = wo + v - cnt;
#pragma unroll
    for (int i = 0; i < 8; i++) {
        g_slot[b * SS + base + i] = loc[i] ? excl : -1;
        excl += loc[i];
    }
    if (t == 255) {
        int tot = wo + v;
        g_nvalid[b] = tot;
        g_npad[b]   = (tot + 127) & ~127;
    }
}

// QKV: grid=(4, 128, 3). z: 0=Q, 1=K(compacted rows), 2=V(transposed+compacted)
__global__ void __launch_bounds__(256, 2)
qkv_mm(int dummy) {
    extern __shared__ char smem[];
    const int z = blockIdx.z;
    float acc[2][8][4];
    gemm_pipe(g_xh, g_xl, g_wh + z * DD * DD, g_wl + z * DD * DD,
              DD, DD, DD, smem, acc);

    const int lane = threadIdx.x & 31;
    const int w = threadIdx.x >> 5;
    const int wm = w & 3, wn = w >> 2;
    const int mb = blockIdx.y * 128 + wm * 32 + (lane >> 2);
    const int nb = blockIdx.x * 128 + wn * 64 + (lane & 3) * 2;
    const int b = mb >> 11;

    if (z == 0) {
        store_acc_split(g_qh, g_ql, DD, acc);
    } else if (z == 1) {
        // K: scatter rows to compacted slots
#pragma unroll
        for (int mi = 0; mi < 2; mi++) {
#pragma unroll
            for (int half = 0; half < 2; half++) {
                int s = (mb & 2047) + mi * 16 + half * 8;
                int slot = g_slot[b * SS + s];
                if (slot < 0) continue;
                size_t rowo = ((size_t)b * SS + slot) * DD;
#pragma unroll
                for (int nj = 0; nj < 8; nj++) {
                    float a = acc[mi][nj][half * 2], c = acc[mi][nj][half * 2 + 1];
                    *reinterpret_cast<uint32_t*>(g_kh + rowo + nb + nj * 8) =
                        pack_split(a, c);
                    *reinterpret_cast<uint32_t*>(g_kl + rowo + nb + nj * 8) =
                        pack_split(a - bfv(a), c - bfv(c));
                }
            }
        }
    } else {
        // V: transpose + scatter columns to compacted slots
        __nv_bfloat16* vh = g_vth + (size_t)b * DD * SS;
        __nv_bfloat16* vl = g_vtl + (size_t)b * DD * SS;
#pragma unroll
        for (int mi = 0; mi < 2; mi++) {
#pragma unroll
            for (int half = 0; half < 2; half++) {
                int s = (mb & 2047) + mi * 16 + half * 8;
                int slot = g_slot[b * SS + s];
                if (slot < 0) continue;
#pragma unroll
                for (int nj = 0; nj < 8; nj++) {
                    int d = nb + nj * 8;
                    float v0 = acc[mi][nj][half * 2];
                    float v1 = acc[mi][nj][half * 2 + 1];
                    vh[(size_t)d * SS + slot]       = __float2bfloat16(v0);
                    vl[(size_t)d * SS + slot]       = __float2bfloat16(v0 - bfv(v0));
                    vh[(size_t)(d + 1) * SS + slot] = __float2bfloat16(v1);
                    vl[(size_t)(d + 1) * SS + slot] = __float2bfloat16(v1 - bfv(v1));
                }
            }
        }
    }
}

// scores over compacted keys: grid=(16,16,8); CTAs beyond npad exit
__global__ void __launch_bounds__(256, 2)
scores_mm(int dummy) {
    extern __shared__ char smem[];
    const int b = blockIdx.z;
    const int npad = g_npad[b];
    if (blockIdx.x * 128 >= npad) return;
    const int nv = g_nvalid[b];

    float acc[2][8][4];
    gemm_pipe(g_qh + (size_t)b * SS * DD, g_ql + (size_t)b * SS * DD,
              g_kh + (size_t)b * SS * DD, g_kl + (size_t)b * SS * DD,
              DD, DD, DD, smem, acc);

    const int lane = threadIdx.x & 31;
    const int w = threadIdx.x >> 5;
    const int wm = w & 3, wn = w >> 2;
    const int mb = blockIdx.y * 128 + wm * 32 + (lane >> 2);
    const int nb = blockIdx.x * 128 + wn * 64 + (lane & 3) * 2;
    const float inv_scale = 0.0220970869120796101f;  // 1/sqrt(2048)
    float* Scb = g_sc + (size_t)b * SS * SS;

#pragma unroll
    for (int nj = 0; nj < 8; nj++) {
        int n = nb + nj * 8;
#pragma unroll
        for (int mi = 0; mi < 2; mi++) {
            int m = mb + mi * 16;
            float r0 = (n     < nv) ? acc[mi][nj][0] * inv_scale : -1e30f;
            float r1 = (n + 1 < nv) ? acc[mi][nj][1] * inv_scale : -1e30f;
            float r2 = (n     < nv) ? acc[mi][nj][2] * inv_scale : -1e30f;
            float r3 = (n + 1 < nv) ? acc[mi][nj][3] * inv_scale : -1e30f;
            *reinterpret_cast<float2*>(Scb + (size_t)m * SS + n) = make_float2(r0, r1);
            *reinterpret_cast<float2*>(Scb + (size_t)(m + 8) * SS + n) = make_float2(r2, r3);
        }
    }
}

// softmax over compacted width: one block per (b,row)
__global__ void __launch_bounds__(256)
softmax_kernel() {
    __shared__ float red[8];
    const int b = blockIdx.x >> 11;
    const int W = g_npad[b];
    const size_t base = (size_t)blockIdx.x * SS;
    const float* p = g_sc + base;
    const int tid = threadIdx.x;

    float4 v[2];
    int ni = 0;
    float mx = -1e38f;
    for (int x = tid * 4; x < W; x += 1024) {
        v[ni] = *reinterpret_cast<const float4*>(p + x);
        mx = fmaxf(mx, fmaxf(fmaxf(v[ni].x, v[ni].y), fmaxf(v[ni].z, v[ni].w)));
        ni++;
    }
#pragma unroll
    for (int o = 16; o > 0; o >>= 1) mx = fmaxf(mx, __shfl_xor_sync(0xffffffffu, mx, o));
    if ((tid & 31) == 0) red[tid >> 5] = mx;
    __syncthreads();
    mx = red[0];
#pragma unroll
    for (int wi = 1; wi < 8; wi++) mx = fmaxf(mx, red[wi]);

    float sum = 0.0f;
    for (int i = 0; i < ni; i++) {
        v[i].x = __expf(v[i].x - mx);
        v[i].y = __expf(v[i].y - mx);
        v[i].z = __expf(v[i].z - mx);
        v[i].w = __expf(v[i].w - mx);
        sum += (v[i].x + v[i].y) + (v[i].z + v[i].w);
    }
#pragma unroll
    for (int o = 16; o > 0; o >>= 1) sum += __shfl_xor_sync(0xffffffffu, sum, o);
    __syncthreads();
    if ((tid & 31) == 0) red[tid >> 5] = sum;
    __syncthreads();
    sum = 0.0f;
#pragma unroll
    for (int wi = 0; wi < 8; wi++) sum += red[wi];

    const float rinv = 1.0f / sum;
    int i = 0;
    for (int x = tid * 4; x < W; x += 1024, i++) {
        float px = v[i].x * rinv, py = v[i].y * rinv;
        float pz = v[i].z * rinv, pw = v[i].w * rinv;
        *reinterpret_cast<uint2*>(g_ph + base + x) =
            make_uint2(pack_split(px, py), pack_split(pz, pw));
        *reinterpret_cast<uint2*>(g_pl + base + x) =
            make_uint2(pack_split(px - bfv(px), py - bfv(py)),
                       pack_split(pz - bfv(pz), pw - bfv(pw)));
    }
}

// PV over compacted K-dim: grid=(4,16,8)
__global__ void __launch_bounds__(256, 2)
pv_mm(float* __restrict__ out) {
    extern __shared__ char smem[];
    const int b = blockIdx.z;
    const int W = g_npad[b];
    float acc[2][8][4];
    gemm_pipe(g_ph + (size_t)b * SS * SS, g_pl + (size_t)b * SS * SS,
              g_vth + (size_t)b * DD * SS, g_vtl + (size_t)b * DD * SS,
              W, SS, SS, smem, acc);
    store_acc_f32(out + (size_t)b * SS * DD, DD, acc);
}

// ---------------------------------------------------------------------------
extern "C" void kernel_launch(void* const* d_in, const int* in_sizes, int n_in,
                              void* d_out, int out_size) {
    const float* X    = (const float*)d_in[0];
    const int*   mask = (const int*)  d_in[1];
    const float* Wq   = (const float*)d_in[2];
    const float* Wk   = (const float*)d_in[3];
    const float* Wv   = (const float*)d_in[4];
    float* out = (float*)d_out;

    static bool attr_done = false;
    if (!attr_done) {
        cudaFuncSetAttribute(qkv_mm,    cudaFuncAttributeMaxDynamicSharedMemorySize, 2 * STG);
        cudaFuncSetAttribute(scores_mm, cudaFuncAttributeMaxDynamicSharedMemorySize, 2 * STG);
        cudaFuncSetAttribute(pv_mm,     cudaFuncAttributeMaxDynamicSharedMemorySize, 2 * STG);
        attr_done = true;
    }

    __nv_bfloat16 *xh, *xl, *wh, *wl;
    cudaGetSymbolAddress((void**)&xh, g_xh);
    cudaGetSymbolAddress((void**)&xl, g_xl);
    cudaGetSymbolAddress((void**)&wh, g_wh);
    cudaGetSymbolAddress((void**)&wl, g_wl);

    const int nX4 = (BB * SS * DD) / 4;
    const int nW4 = (DD * DD) / 4;
    split_kernel<<<(nX4 + 255) / 256, 256>>>(X, xh, xl, nX4);
    split_kernel<<<(nW4 + 255) / 256, 256>>>(Wq, wh,            wl,            nW4);
    split_kernel<<<(nW4 + 255) / 256, 256>>>(Wk, wh + DD * DD,  wl + DD * DD,  nW4);
    split_kernel<<<(nW4 + 255) / 256, 256>>>(Wv, wh + 2*DD*DD,  wl + 2*DD*DD,  nW4);
    build_index<<<BB, 256>>>(mask);

    dim3 blk(256);
    qkv_mm<<<dim3(DD / 128, (BB * SS) / 128, 3), blk, 2 * STG>>>(0);
    scores_mm<<<dim3(SS / 128, SS / 128, BB), blk, 2 * STG>>>(0);
    softmax_kernel<<<BB * SS, 256>>>();
    pv_mm<<<dim3(DD / 128, SS / 128, BB), blk, 2 * STG>>>(out);
}